// round 8
// baseline (speedup 1.0000x reference)
#include <cuda_runtime.h>

// Problem constants (fixed by the dataset)
#define B_    64
#define OBJS_ 2048
#define D_    256
#define K_    2
#define N_    (B_*OBJS_)          // 131072
#define BDK   (B_*D_*K_)          // 32768
#define NK    (N_*K_)             // 262144

#define CPS   32                  // CTAs per scene
#define CHUNK 64                  // rows per CTA (64 KB in smem)
#define NCTA  (B_*CPS)            // 2048
#define THREADS 256
#define NWARP 8
#define ROWS_PER_WARP (CHUNK/NWARP)   // 8
#define SMEM_DYN (CHUNK*D_*4)     // 64 KB x-chunk

typedef unsigned long long u64;

// Scratch (device globals — allocation-free rule).
// All accumulators are zero on first launch (static init) and are reset by the
// per-scene finalizing CTA at the end of each launch -> graph-replay safe.
__device__ float g_ctxsum[B_*D_];   // per-scene column sums (REDG accum)
__device__ float g_feat[B_*D_*K_];  // per-scene pooled features (REDG accum)
__device__ float g_zs[B_*K_];       // per-scene softmax denominators
__device__ float g_z[NK];           // per-object unnormalized numerators
__device__ int   g_ready[B_];       // pass-1 arrival counts
__device__ int   g_done[B_];        // pass-2 completion counts

// ---- packed f32x2 helpers --------------------------------------------------
__device__ __forceinline__ u64 pack2(float lo, float hi) {
    u64 r; asm("mov.b64 %0,{%1,%2};" : "=l"(r) : "f"(lo), "f"(hi)); return r;
}
__device__ __forceinline__ float2 unpack2(u64 v) {
    float lo, hi; asm("mov.b64 {%0,%1},%2;" : "=f"(lo), "=f"(hi) : "l"(v));
    return make_float2(lo, hi);
}
__device__ __forceinline__ u64 add2(u64 a, u64 b) {
    u64 d; asm("add.rn.f32x2 %0,%1,%2;" : "=l"(d) : "l"(a), "l"(b)); return d;
}
__device__ __forceinline__ u64 fma2(u64 a, u64 b, u64 c) {
    u64 d; asm("fma.rn.f32x2 %0,%1,%2,%3;" : "=l"(d) : "l"(a), "l"(b), "l"(c)); return d;
}
__device__ __forceinline__ u64 abs2(u64 a) {   // clear both sign bits (ALU pipe)
    u64 d; asm("and.b64 %0,%1,0x7FFFFFFF7FFFFFFF;" : "=l"(d) : "l"(a)); return d;
}

// ---------------------------------------------------------------------------
__global__ __launch_bounds__(THREADS, 2) void fusedK(
    const float* __restrict__ x,
    const float* __restrict__ att,
    const float* __restrict__ scale,
    const float* __restrict__ cb,
    const int*   __restrict__ num_objs,
    float*       __restrict__ out,
    int out_size)
{
    extern __shared__ __align__(16) float sx[];        // 64 KB: this CTA's rows
    __shared__ __align__(16) float sctx[D_];           // scene mean context
    __shared__ float sfeat[D_*K_];                     // feature accum (2 KB)
    __shared__ __align__(8) float sz[CHUNK*K_];        // per-row z (512 B)
    __shared__ float sbt[K_];
    __shared__ float szs[K_];
    __shared__ int   slast;

    const int cta   = blockIdx.x;
    const int b     = cta >> 5;          // scene (32 contiguous CTAs/scene)
    const int chunk = cta & 31;
    const int tid   = threadIdx.x;
    const int warp  = tid >> 5, lane = tid & 31;

    // ============ pass 1: DRAM -> SMEM copy + column sums ==================
    {
        const int col4   = tid & 63;          // float4 column
        const int rowgrp = tid >> 6;          // 0..3 (4-row stride)
        const float4* x4 = (const float4*)x
            + ((size_t)(b*OBJS_ + chunk*CHUNK + rowgrp))*64 + col4;
        float4* sx4 = (float4*)sx;
        float4 acc = {0.f,0.f,0.f,0.f};
        #pragma unroll
        for (int i = 0; i < CHUNK/4; i++) {
            float4 v = x4[(size_t)i*4*64];
            sx4[(rowgrp + i*4)*64 + col4] = v;
            acc.x += v.x; acc.y += v.y; acc.z += v.z; acc.w += v.w;
        }
        int c = b*D_ + col4*4;
        atomicAdd(&g_ctxsum[c+0], acc.x);
        atomicAdd(&g_ctxsum[c+1], acc.y);
        atomicAdd(&g_ctxsum[c+2], acc.z);
        atomicAdd(&g_ctxsum[c+3], acc.w);
    }

    // bias_term = channel_bias @ att_shared (tiny, per-CTA redundant)
    if (tid < 64) {
        int k = tid >> 5, l = tid & 31;
        float s = 0.f;
        #pragma unroll
        for (int j = 0; j < 8; j++) s += cb[k*D_ + l + 32*j] * att[l + 32*j];
        #pragma unroll
        for (int m = 16; m; m >>= 1) s += __shfl_xor_sync(0xffffffffu, s, m);
        if (l == 0) sbt[k] = s;
    }
    for (int i = tid; i < D_*K_; i += THREADS) sfeat[i] = 0.f;
    if (tid < K_) szs[tid] = 0.f;

    // ============ scene barrier (arrive-then-wait, deadlock-free) ==========
    __threadfence();
    __syncthreads();
    if (tid == 0) {
        atomicAdd(&g_ready[b], 1);
        volatile int* f = &g_ready[b];
        while (*f < CPS) __nanosleep(64);
    }
    __syncthreads();
    __threadfence();

    // scene mean context
    const float invc = 1.f / fmaxf((float)num_objs[b], 1.f);
    sctx[tid] = g_ctxsum[b*D_ + tid] * invc;
    __syncthreads();

    // ============ pass 2: from SMEM — logits + exp + pooling ===============
    const float bt0 = sbt[0], bt1 = sbt[1];
    const float s0  = scale[0], s1 = scale[1];

    float4 cxa = ((const float4*)sctx)[lane];
    float4 cxb = ((const float4*)sctx)[lane + 32];
    u64 c0 = pack2(cxa.x, cxa.y), c1 = pack2(cxa.z, cxa.w);
    u64 c2 = pack2(cxb.x, cxb.y), c3 = pack2(cxb.z, cxb.w);

    float4 a_a = ((const float4*)att)[lane];
    float4 a_b = ((const float4*)att)[lane + 32];
    // lrelu(t) = 0.6t + 0.4|t|  ->  a*lrelu = (0.6a)*t + (0.4a)*|t|
    const u64 a6_0 = pack2(0.6f*a_a.x, 0.6f*a_a.y), a6_1 = pack2(0.6f*a_a.z, 0.6f*a_a.w);
    const u64 a6_2 = pack2(0.6f*a_b.x, 0.6f*a_b.y), a6_3 = pack2(0.6f*a_b.z, 0.6f*a_b.w);
    const u64 a4_0 = pack2(0.4f*a_a.x, 0.4f*a_a.y), a4_1 = pack2(0.4f*a_a.z, 0.4f*a_a.w);
    const u64 a4_2 = pack2(0.4f*a_b.x, 0.4f*a_b.y), a4_3 = pack2(0.4f*a_b.z, 0.4f*a_b.w);

    u64 f0_0=0,f0_1=0,f0_2=0,f0_3=0;   // k=0 pooled features (packed)
    u64 f1_0=0,f1_1=0,f1_2=0,f1_3=0;   // k=1
    float zs0 = 0.f, zs1 = 0.f;

    #pragma unroll
    for (int r = 0; r < ROWS_PER_WARP; r++) {
        const int lrow = warp*ROWS_PER_WARP + r;
        const ulonglong2* xr = (const ulonglong2*)(sx + lrow*D_);
        ulonglong2 xa = xr[lane];
        ulonglong2 xb = xr[lane + 32];

        u64 t0 = add2(xa.x, c0), t1 = add2(xa.y, c1);
        u64 t2 = add2(xb.x, c2), t3 = add2(xb.y, c3);

        u64 accA = fma2(a6_0, t0, fma2(a4_0, abs2(t0), 0ull));
        accA     = fma2(a6_1, t1, fma2(a4_1, abs2(t1), accA));
        u64 accB = fma2(a6_2, t2, fma2(a4_2, abs2(t2), 0ull));
        accB     = fma2(a6_3, t3, fma2(a4_3, abs2(t3), accB));
        float2 p = unpack2(add2(accA, accB));
        float acc = p.x + p.y;
        #pragma unroll
        for (int m = 16; m; m >>= 1)
            acc += __shfl_xor_sync(0xffffffffu, acc, m);

        float z0 = __expf((acc + bt0) * s0);
        float z1 = __expf((acc + bt1) * s1);
        zs0 += z0; zs1 += z1;
        if (lane == 0)
            *(float2*)&sz[lrow*2] = make_float2(z0, z1);

        u64 zz0 = pack2(z0, z0), zz1 = pack2(z1, z1);
        f0_0 = fma2(xa.x, zz0, f0_0); f0_1 = fma2(xa.y, zz0, f0_1);
        f0_2 = fma2(xb.x, zz0, f0_2); f0_3 = fma2(xb.y, zz0, f0_3);
        f1_0 = fma2(xa.x, zz1, f1_0); f1_1 = fma2(xa.y, zz1, f1_1);
        f1_2 = fma2(xb.x, zz1, f1_2); f1_3 = fma2(xb.y, zz1, f1_3);
    }

    // cross-warp combine (lanes hit distinct smem addrs within a warp)
    {
        int d0 = 4*lane, d1 = 128 + 4*lane;
        float2 v;
        v = unpack2(f0_0); atomicAdd(&sfeat[(d0+0)*2+0], v.x); atomicAdd(&sfeat[(d0+1)*2+0], v.y);
        v = unpack2(f0_1); atomicAdd(&sfeat[(d0+2)*2+0], v.x); atomicAdd(&sfeat[(d0+3)*2+0], v.y);
        v = unpack2(f0_2); atomicAdd(&sfeat[(d1+0)*2+0], v.x); atomicAdd(&sfeat[(d1+1)*2+0], v.y);
        v = unpack2(f0_3); atomicAdd(&sfeat[(d1+2)*2+0], v.x); atomicAdd(&sfeat[(d1+3)*2+0], v.y);
        v = unpack2(f1_0); atomicAdd(&sfeat[(d0+0)*2+1], v.x); atomicAdd(&sfeat[(d0+1)*2+1], v.y);
        v = unpack2(f1_1); atomicAdd(&sfeat[(d0+2)*2+1], v.x); atomicAdd(&sfeat[(d0+3)*2+1], v.y);
        v = unpack2(f1_2); atomicAdd(&sfeat[(d1+0)*2+1], v.x); atomicAdd(&sfeat[(d1+1)*2+1], v.y);
        v = unpack2(f1_3); atomicAdd(&sfeat[(d1+2)*2+1], v.x); atomicAdd(&sfeat[(d1+3)*2+1], v.y);
    }
    if (lane == 0) { atomicAdd(&szs[0], zs0); atomicAdd(&szs[1], zs1); }
    __syncthreads();

    // publish: fire-and-forget REDG into per-scene accumulators + z write
    for (int i = tid; i < D_*K_; i += THREADS)
        atomicAdd(&g_feat[b*(D_*K_) + i], sfeat[i]);
    if (tid < K_) atomicAdd(&g_zs[b*K_ + tid], szs[tid]);
    {
        float2* gz2 = ((float2*)g_z) + b*OBJS_ + chunk*CHUNK;
        const float2* z2 = (const float2*)sz;
        for (int i = tid; i < CHUNK; i += THREADS) gz2[i] = z2[i];
    }

    __threadfence();
    __syncthreads();
    if (tid == 0) slast = (atomicAdd(&g_done[b], 1) == CPS-1);
    __syncthreads();

    // ============ last CTA of the scene: finalize + reset ==================
    if (slast) {
        __threadfence();
        const bool full_out = (out_size >= BDK + NK);
        float zt0 = g_zs[b*K_ + 0], zt1 = g_zs[b*K_ + 1];
        float inv0 = 1.f/zt0, inv1 = 1.f/zt1;

        if (out_size >= BDK) {                 // features at offset 0: [B,D,K]
            float2 v = ((const float2*)g_feat)[b*D_ + tid];
            ((float2*)out)[b*D_ + tid] = make_float2(v.x*inv0, v.y*inv1);
        }
        if (full_out || out_size == NK) {      // attention weights [N,K]
            int obase = full_out ? (BDK/2) : 0;
            const float2* gz2 = ((const float2*)g_z) + b*OBJS_;
            float2* o2 = ((float2*)out) + obase + b*OBJS_;
            for (int i = tid; i < OBJS_; i += THREADS) {
                float2 z = gz2[i];
                o2[i] = make_float2(z.x*inv0, z.y*inv1);
            }
        }

        __syncthreads();                       // reads done before resets
        g_ctxsum[b*D_ + tid] = 0.f;
        for (int i = tid; i < D_*K_; i += THREADS) g_feat[b*(D_*K_) + i] = 0.f;
        if (tid < K_) g_zs[b*K_ + tid] = 0.f;
        if (tid == 0) { g_done[b] = 0; g_ready[b] = 0; }
    }
}

// ---------------------------------------------------------------------------
extern "C" void kernel_launch(void* const* d_in, const int* in_sizes, int n_in,
                              void* d_out, int out_size)
{
    const float* x        = (const float*)d_in[0];  // [N, D]
    const int*   num_objs = (const int*)  d_in[1];  // [B]
    const float* att      = (const float*)d_in[2];  // [1, D]
    const float* scale    = (const float*)d_in[3];  // [K, 1]
    const float* cb       = (const float*)d_in[4];  // [K, D]
    float*       out      = (float*)d_out;

    static int smem_set = 0;
    if (!smem_set) {
        cudaFuncSetAttribute(fusedK, cudaFuncAttributeMaxDynamicSharedMemorySize,
                             SMEM_DYN);
        smem_set = 1;
    }
    fusedK<<<NCTA, THREADS, SMEM_DYN>>>(x, att, scale, cb, num_objs, out, out_size);
}

// round 9
// speedup vs baseline: 2.2297x; 2.2297x over previous
#include <cuda_runtime.h>

// Problem constants (fixed by the dataset)
#define B_    64
#define OBJS_ 2048
#define D_    256
#define K_    2
#define N_    (B_*OBJS_)          // 131072
#define BDK   (B_*D_*K_)          // 32768
#define NK    (N_*K_)             // 262144

#define SPW   32                  // scenes per wave (64 MB working set fits L2)
#define CPS   16                  // CTAs per scene
#define NCTA  (SPW*CPS)           // 512 — co-resident at 4 CTAs/SM (592 slots)
#define THREADS 128
#define CHUNK (OBJS_/CPS)         // 128 rows per CTA per wave

typedef unsigned long long u64;

// Scratch (device globals — allocation-free rule). Zero-init at load; every
// field is reset by its scene's finalizer / the last-ack CTA -> replay-safe.
__device__ float g_ctxsum[B_*D_];   // per-scene column sums (REDG accum)
__device__ float g_feat[B_*D_*K_];  // per-scene pooled features (REDG accum)
__device__ float g_zs[B_*K_];       // per-scene softmax denominators
__device__ float g_z[NK];           // per-object unnormalized numerators
__device__ int   g_done[B_];        // per-scene pass-2 completion counts
__device__ int   g_bar[2];          // grid-barrier counters
__device__ int   g_ack;             // end-of-kernel ack

// ---- packed f32x2 helpers --------------------------------------------------
__device__ __forceinline__ u64 pack2(float lo, float hi) {
    u64 r; asm("mov.b64 %0,{%1,%2};" : "=l"(r) : "f"(lo), "f"(hi)); return r;
}
__device__ __forceinline__ float2 unpack2(u64 v) {
    float lo, hi; asm("mov.b64 {%0,%1},%2;" : "=f"(lo), "=f"(hi) : "l"(v));
    return make_float2(lo, hi);
}
__device__ __forceinline__ u64 add2(u64 a, u64 b) {
    u64 d; asm("add.rn.f32x2 %0,%1,%2;" : "=l"(d) : "l"(a), "l"(b)); return d;
}
__device__ __forceinline__ u64 fma2(u64 a, u64 b, u64 c) {
    u64 d; asm("fma.rn.f32x2 %0,%1,%2,%3;" : "=l"(d) : "l"(a), "l"(b), "l"(c)); return d;
}
__device__ __forceinline__ u64 abs2(u64 a) {
    u64 d; asm("and.b64 %0,%1,0x7FFFFFFF7FFFFFFF;" : "=l"(d) : "l"(a)); return d;
}

// grid barrier: all NCTA CTAs co-resident by construction
__device__ __forceinline__ void gridbar(int i, int tid) {
    __threadfence();
    __syncthreads();
    if (tid == 0) {
        atomicAdd(&g_bar[i], 1);
        volatile int* c = &g_bar[i];
        while (*c < NCTA) __nanosleep(32);
    }
    __syncthreads();
    __threadfence();
}

// ---------------------------------------------------------------------------
__global__ __launch_bounds__(THREADS, 4) void fusedK(
    const float* __restrict__ x,
    const float* __restrict__ att,
    const float* __restrict__ scale,
    const float* __restrict__ cb,
    const int*   __restrict__ num_objs,
    float*       __restrict__ out,
    int out_size)
{
    __shared__ __align__(16) float sctx[D_];           // scene mean context
    __shared__ float sfeat[D_*K_];                     // feature accum (2 KB)
    __shared__ __align__(8) float sz[CHUNK*K_];        // per-row z (1 KB)
    __shared__ float sbt[K_];
    __shared__ float szs[K_];
    __shared__ int   sflag;

    const int cta   = blockIdx.x;
    const int sidx  = cta >> 4;           // scene within wave (0..31)
    const int chunk = cta & 15;
    const int b0    = sidx;               // wave-0 scene
    const int b1    = SPW + sidx;         // wave-1 scene
    const int tid   = threadIdx.x;
    const int warp  = tid >> 5, lane = tid & 31;

    const bool full_out = (out_size >= BDK + NK);
    const bool attn_any = full_out || (out_size == NK);

    // per-lane invariant att factors: lrelu(t)=0.6t+0.4|t|
    float4 a_a = ((const float4*)att)[lane];
    float4 a_b = ((const float4*)att)[lane + 32];
    const u64 a6_0 = pack2(0.6f*a_a.x, 0.6f*a_a.y), a6_1 = pack2(0.6f*a_a.z, 0.6f*a_a.w);
    const u64 a6_2 = pack2(0.6f*a_b.x, 0.6f*a_b.y), a6_3 = pack2(0.6f*a_b.z, 0.6f*a_b.w);
    const u64 a4_0 = pack2(0.4f*a_a.x, 0.4f*a_a.y), a4_1 = pack2(0.4f*a_a.z, 0.4f*a_a.w);
    const u64 a4_2 = pack2(0.4f*a_b.x, 0.4f*a_b.y), a4_3 = pack2(0.4f*a_b.z, 0.4f*a_b.w);

    // bias_term (tiny, per-CTA redundant)
    if (tid < 64) {
        int k = tid >> 5, l = tid & 31;
        float s = 0.f;
        #pragma unroll
        for (int j = 0; j < 8; j++) s += cb[k*D_ + l + 32*j] * att[l + 32*j];
        #pragma unroll
        for (int m = 16; m; m >>= 1) s += __shfl_xor_sync(0xffffffffu, s, m);
        if (l == 0) sbt[k] = s;
    }

    // ================= PHASE A: pass-1 of wave 0 (all 4 warps) =============
    {
        const int col4 = tid & 63, rg = tid >> 6;     // 64 cols x 2 rowgroups
        const float4* x4 = (const float4*)x
            + ((size_t)(b0*OBJS_ + chunk*CHUNK + rg))*64 + col4;
        float4 acc = {0.f,0.f,0.f,0.f};
        #pragma unroll 16
        for (int i = 0; i < CHUNK/2; i++) {           // stride 2 rows
            float4 v = x4[(size_t)i*128];
            acc.x += v.x; acc.y += v.y; acc.z += v.z; acc.w += v.w;
        }
        int c = b0*D_ + col4*4;
        atomicAdd(&g_ctxsum[c+0], acc.x);
        atomicAdd(&g_ctxsum[c+1], acc.y);
        atomicAdd(&g_ctxsum[c+2], acc.z);
        atomicAdd(&g_ctxsum[c+3], acc.w);
    }
    for (int i = tid; i < D_*K_; i += THREADS) sfeat[i] = 0.f;
    if (tid < K_) szs[tid] = 0.f;

    gridbar(0, tid);

    const float bt0 = sbt[0], bt1 = sbt[1];
    const float s0  = scale[0], s1 = scale[1];

    // wave-0 ctx into smem
    {
        const float invc = 1.f / fmaxf((float)num_objs[b0], 1.f);
        sctx[tid]       = g_ctxsum[b0*D_ + tid]       * invc;
        sctx[tid + 128] = g_ctxsum[b0*D_ + tid + 128] * invc;
    }
    __syncthreads();

    // ============ PHASE B: warps 0-1 pass-2(w0); warps 2-3 pass-1(w1) ======
    if (warp < 2) {
        float4 cxa = ((const float4*)sctx)[lane];
        float4 cxb = ((const float4*)sctx)[lane + 32];
        u64 c0 = pack2(cxa.x, cxa.y), c1 = pack2(cxa.z, cxa.w);
        u64 c2 = pack2(cxb.x, cxb.y), c3 = pack2(cxb.z, cxb.w);

        u64 f0_0=0,f0_1=0,f0_2=0,f0_3=0;
        u64 f1_0=0,f1_1=0,f1_2=0,f1_3=0;
        float zs0 = 0.f, zs1 = 0.f;
        const int rowbase = b0*OBJS_ + chunk*CHUNK + warp*(CHUNK/2);

        #pragma unroll 4
        for (int r = 0; r < CHUNK/2; r++) {           // 64 rows per warp
            const int lrow = warp*(CHUNK/2) + r;
            const ulonglong2* xr = (const ulonglong2*)(x + (size_t)(rowbase + r)*D_);
            ulonglong2 xa = xr[lane];
            ulonglong2 xb = xr[lane + 32];

            u64 t0 = add2(xa.x, c0), t1 = add2(xa.y, c1);
            u64 t2 = add2(xb.x, c2), t3 = add2(xb.y, c3);
            u64 accA = fma2(a6_0, t0, fma2(a4_0, abs2(t0), 0ull));
            accA     = fma2(a6_1, t1, fma2(a4_1, abs2(t1), accA));
            u64 accB = fma2(a6_2, t2, fma2(a4_2, abs2(t2), 0ull));
            accB     = fma2(a6_3, t3, fma2(a4_3, abs2(t3), accB));
            float2 p = unpack2(add2(accA, accB));
            float acc = p.x + p.y;
            #pragma unroll
            for (int m = 16; m; m >>= 1)
                acc += __shfl_xor_sync(0xffffffffu, acc, m);

            float z0 = __expf((acc + bt0) * s0);
            float z1 = __expf((acc + bt1) * s1);
            zs0 += z0; zs1 += z1;
            if (lane == 0) *(float2*)&sz[lrow*2] = make_float2(z0, z1);

            u64 zz0 = pack2(z0, z0), zz1 = pack2(z1, z1);
            f0_0 = fma2(xa.x, zz0, f0_0); f0_1 = fma2(xa.y, zz0, f0_1);
            f0_2 = fma2(xb.x, zz0, f0_2); f0_3 = fma2(xb.y, zz0, f0_3);
            f1_0 = fma2(xa.x, zz1, f1_0); f1_1 = fma2(xa.y, zz1, f1_1);
            f1_2 = fma2(xb.x, zz1, f1_2); f1_3 = fma2(xb.y, zz1, f1_3);
        }
        int d0 = 4*lane, d1 = 128 + 4*lane;
        float2 v;
        v = unpack2(f0_0); atomicAdd(&sfeat[(d0+0)*2+0], v.x); atomicAdd(&sfeat[(d0+1)*2+0], v.y);
        v = unpack2(f0_1); atomicAdd(&sfeat[(d0+2)*2+0], v.x); atomicAdd(&sfeat[(d0+3)*2+0], v.y);
        v = unpack2(f0_2); atomicAdd(&sfeat[(d1+0)*2+0], v.x); atomicAdd(&sfeat[(d1+1)*2+0], v.y);
        v = unpack2(f0_3); atomicAdd(&sfeat[(d1+2)*2+0], v.x); atomicAdd(&sfeat[(d1+3)*2+0], v.y);
        v = unpack2(f1_0); atomicAdd(&sfeat[(d0+0)*2+1], v.x); atomicAdd(&sfeat[(d0+1)*2+1], v.y);
        v = unpack2(f1_1); atomicAdd(&sfeat[(d0+2)*2+1], v.x); atomicAdd(&sfeat[(d0+3)*2+1], v.y);
        v = unpack2(f1_2); atomicAdd(&sfeat[(d1+0)*2+1], v.x); atomicAdd(&sfeat[(d1+1)*2+1], v.y);
        v = unpack2(f1_3); atomicAdd(&sfeat[(d1+2)*2+1], v.x); atomicAdd(&sfeat[(d1+3)*2+1], v.y);
        if (lane == 0) { atomicAdd(&szs[0], zs0); atomicAdd(&szs[1], zs1); }
    } else {
        // pass-1 of wave 1: 64 threads, one column-float4 each, 128 rows
        const int col4 = tid & 63;
        const float4* x4 = (const float4*)x
            + ((size_t)(b1*OBJS_ + chunk*CHUNK))*64 + col4;
        float4 acc = {0.f,0.f,0.f,0.f};
        #pragma unroll 16
        for (int i = 0; i < CHUNK; i++) {
            float4 v = x4[(size_t)i*64];
            acc.x += v.x; acc.y += v.y; acc.z += v.z; acc.w += v.w;
        }
        int c = b1*D_ + col4*4;
        atomicAdd(&g_ctxsum[c+0], acc.x);
        atomicAdd(&g_ctxsum[c+1], acc.y);
        atomicAdd(&g_ctxsum[c+2], acc.z);
        atomicAdd(&g_ctxsum[c+3], acc.w);
    }
    __syncthreads();

    // publish wave-0 partials
    for (int i = tid; i < D_*K_; i += THREADS)
        atomicAdd(&g_feat[b0*(D_*K_) + i], sfeat[i]);
    if (tid < K_) atomicAdd(&g_zs[b0*K_ + tid], szs[tid]);
    {
        float2* gz2 = ((float2*)g_z) + b0*OBJS_ + chunk*CHUNK;
        const float2* z2 = (const float2*)sz;
        for (int i = tid; i < CHUNK; i += THREADS) gz2[i] = z2[i];
    }
    __threadfence();
    __syncthreads();
    if (tid == 0) sflag = (atomicAdd(&g_done[b0], 1) == CPS-1);
    __syncthreads();

    // last CTA of a wave-0 scene: finalize it (overlaps others' phase B/C)
    if (sflag) {
        __threadfence();
        float zt0 = g_zs[b0*K_ + 0], zt1 = g_zs[b0*K_ + 1];
        float inv0 = 1.f/zt0, inv1 = 1.f/zt1;
        if (out_size >= BDK) {
            for (int i = tid; i < D_; i += THREADS) {
                float2 v = ((const float2*)g_feat)[b0*D_ + i];
                ((float2*)out)[b0*D_ + i] = make_float2(v.x*inv0, v.y*inv1);
            }
        }
        if (attn_any) {
            int obase = full_out ? (BDK/2) : 0;
            const float2* gz2 = ((const float2*)g_z) + b0*OBJS_;
            float2* o2 = ((float2*)out) + obase + b0*OBJS_;
            for (int i = tid; i < OBJS_; i += THREADS) {
                float2 z = gz2[i];
                o2[i] = make_float2(z.x*inv0, z.y*inv1);
            }
        }
        __syncthreads();
        for (int i = tid; i < D_*K_; i += THREADS) g_feat[b0*(D_*K_) + i] = 0.f;
        g_ctxsum[b0*D_ + tid] = 0.f; g_ctxsum[b0*D_ + tid + 128] = 0.f;
        if (tid < K_) g_zs[b0*K_ + tid] = 0.f;
        if (tid == 0) g_done[b0] = 0;
    }

    // reset smem accumulators for wave 1 (gridbar syncs before use)
    for (int i = tid; i < D_*K_; i += THREADS) sfeat[i] = 0.f;
    if (tid < K_) szs[tid] = 0.f;

    gridbar(1, tid);

    // wave-1 ctx into smem
    {
        const float invc = 1.f / fmaxf((float)num_objs[b1], 1.f);
        sctx[tid]       = g_ctxsum[b1*D_ + tid]       * invc;
        sctx[tid + 128] = g_ctxsum[b1*D_ + tid + 128] * invc;
    }
    __syncthreads();

    // ================= PHASE C: pass-2 of wave 1 (all 4 warps) =============
    {
        float4 cxa = ((const float4*)sctx)[lane];
        float4 cxb = ((const float4*)sctx)[lane + 32];
        u64 c0 = pack2(cxa.x, cxa.y), c1 = pack2(cxa.z, cxa.w);
        u64 c2 = pack2(cxb.x, cxb.y), c3 = pack2(cxb.z, cxb.w);

        u64 f0_0=0,f0_1=0,f0_2=0,f0_3=0;
        u64 f1_0=0,f1_1=0,f1_2=0,f1_3=0;
        float zs0 = 0.f, zs1 = 0.f;
        const int rpw = CHUNK/4;                       // 32 rows per warp
        const int rowbase = b1*OBJS_ + chunk*CHUNK + warp*rpw;

        #pragma unroll 4
        for (int r = 0; r < rpw; r++) {
            const int lrow = warp*rpw + r;
            const ulonglong2* xr = (const ulonglong2*)(x + (size_t)(rowbase + r)*D_);
            ulonglong2 xa = xr[lane];
            ulonglong2 xb = xr[lane + 32];

            u64 t0 = add2(xa.x, c0), t1 = add2(xa.y, c1);
            u64 t2 = add2(xb.x, c2), t3 = add2(xb.y, c3);
            u64 accA = fma2(a6_0, t0, fma2(a4_0, abs2(t0), 0ull));
            accA     = fma2(a6_1, t1, fma2(a4_1, abs2(t1), accA));
            u64 accB = fma2(a6_2, t2, fma2(a4_2, abs2(t2), 0ull));
            accB     = fma2(a6_3, t3, fma2(a4_3, abs2(t3), accB));
            float2 p = unpack2(add2(accA, accB));
            float acc = p.x + p.y;
            #pragma unroll
            for (int m = 16; m; m >>= 1)
                acc += __shfl_xor_sync(0xffffffffu, acc, m);

            float z0 = __expf((acc + bt0) * s0);
            float z1 = __expf((acc + bt1) * s1);
            zs0 += z0; zs1 += z1;
            if (lane == 0) *(float2*)&sz[lrow*2] = make_float2(z0, z1);

            u64 zz0 = pack2(z0, z0), zz1 = pack2(z1, z1);
            f0_0 = fma2(xa.x, zz0, f0_0); f0_1 = fma2(xa.y, zz0, f0_1);
            f0_2 = fma2(xb.x, zz0, f0_2); f0_3 = fma2(xb.y, zz0, f0_3);
            f1_0 = fma2(xa.x, zz1, f1_0); f1_1 = fma2(xa.y, zz1, f1_1);
            f1_2 = fma2(xb.x, zz1, f1_2); f1_3 = fma2(xb.y, zz1, f1_3);
        }
        int d0 = 4*lane, d1 = 128 + 4*lane;
        float2 v;
        v = unpack2(f0_0); atomicAdd(&sfeat[(d0+0)*2+0], v.x); atomicAdd(&sfeat[(d0+1)*2+0], v.y);
        v = unpack2(f0_1); atomicAdd(&sfeat[(d0+2)*2+0], v.x); atomicAdd(&sfeat[(d0+3)*2+0], v.y);
        v = unpack2(f0_2); atomicAdd(&sfeat[(d1+0)*2+0], v.x); atomicAdd(&sfeat[(d1+1)*2+0], v.y);
        v = unpack2(f0_3); atomicAdd(&sfeat[(d1+2)*2+0], v.x); atomicAdd(&sfeat[(d1+3)*2+0], v.y);
        v = unpack2(f1_0); atomicAdd(&sfeat[(d0+0)*2+1], v.x); atomicAdd(&sfeat[(d0+1)*2+1], v.y);
        v = unpack2(f1_1); atomicAdd(&sfeat[(d0+2)*2+1], v.x); atomicAdd(&sfeat[(d0+3)*2+1], v.y);
        v = unpack2(f1_2); atomicAdd(&sfeat[(d1+0)*2+1], v.x); atomicAdd(&sfeat[(d1+1)*2+1], v.y);
        v = unpack2(f1_3); atomicAdd(&sfeat[(d1+2)*2+1], v.x); atomicAdd(&sfeat[(d1+3)*2+1], v.y);
        if (lane == 0) { atomicAdd(&szs[0], zs0); atomicAdd(&szs[1], zs1); }
    }
    __syncthreads();

    // publish wave-1 partials
    for (int i = tid; i < D_*K_; i += THREADS)
        atomicAdd(&g_feat[b1*(D_*K_) + i], sfeat[i]);
    if (tid < K_) atomicAdd(&g_zs[b1*K_ + tid], szs[tid]);
    {
        float2* gz2 = ((float2*)g_z) + b1*OBJS_ + chunk*CHUNK;
        const float2* z2 = (const float2*)sz;
        for (int i = tid; i < CHUNK; i += THREADS) gz2[i] = z2[i];
    }
    __threadfence();
    __syncthreads();
    if (tid == 0) sflag = (atomicAdd(&g_done[b1], 1) == CPS-1);
    __syncthreads();

    if (sflag) {
        __threadfence();
        float zt0 = g_zs[b1*K_ + 0], zt1 = g_zs[b1*K_ + 1];
        float inv0 = 1.f/zt0, inv1 = 1.f/zt1;
        if (out_size >= BDK) {
            for (int i = tid; i < D_; i += THREADS) {
                float2 v = ((const float2*)g_feat)[b1*D_ + i];
                ((float2*)out)[b1*D_ + i] = make_float2(v.x*inv0, v.y*inv1);
            }
        }
        if (attn_any) {
            int obase = full_out ? (BDK/2) : 0;
            const float2* gz2 = ((const float2*)g_z) + b1*OBJS_;
            float2* o2 = ((float2*)out) + obase + b1*OBJS_;
            for (int i = tid; i < OBJS_; i += THREADS) {
                float2 z = gz2[i];
                o2[i] = make_float2(z.x*inv0, z.y*inv1);
            }
        }
        __syncthreads();
        for (int i = tid; i < D_*K_; i += THREADS) g_feat[b1*(D_*K_) + i] = 0.f;
        g_ctxsum[b1*D_ + tid] = 0.f; g_ctxsum[b1*D_ + tid + 128] = 0.f;
        if (tid < K_) g_zs[b1*K_ + tid] = 0.f;
        if (tid == 0) g_done[b1] = 0;
    }

    // last CTA overall resets the grid-barrier counters for the next replay
    if (tid == 0) {
        int a = atomicAdd(&g_ack, 1);
        if (a == NCTA-1) { g_bar[0] = 0; g_bar[1] = 0; g_ack = 0; }
    }
}

// ---------------------------------------------------------------------------
extern "C" void kernel_launch(void* const* d_in, const int* in_sizes, int n_in,
                              void* d_out, int out_size)
{
    const float* x        = (const float*)d_in[0];  // [N, D]
    const int*   num_objs = (const int*)  d_in[1];  // [B]
    const float* att      = (const float*)d_in[2];  // [1, D]
    const float* scale    = (const float*)d_in[3];  // [K, 1]
    const float* cb       = (const float*)d_in[4];  // [K, D]
    float*       out      = (float*)d_out;

    fusedK<<<NCTA, THREADS>>>(x, att, scale, cb, num_objs, out, out_size);
}

// round 10
// speedup vs baseline: 2.5040x; 1.1230x over previous
#include <cuda_runtime.h>
#include <cstdint>

// Problem constants (fixed by the dataset)
#define B_    64
#define OBJS_ 2048
#define D_    256
#define K_    2
#define N_    (B_*OBJS_)          // 131072
#define BDK   (B_*D_*K_)          // 32768
#define NK    (N_*K_)             // 262144

#define CPS   8                   // CTAs per scene == cluster size
#define NCTA  (B_*CPS)            // 512
#define THREADS 256
#define CHUNK (OBJS_/CPS)         // 256 rows per CTA
#define NWARP 8
#define ROWS_PER_WARP (CHUNK/NWARP)   // 32

typedef unsigned long long u64;

// ---- packed f32x2 helpers --------------------------------------------------
__device__ __forceinline__ u64 pack2(float lo, float hi) {
    u64 r; asm("mov.b64 %0,{%1,%2};" : "=l"(r) : "f"(lo), "f"(hi)); return r;
}
__device__ __forceinline__ float2 unpack2(u64 v) {
    float lo, hi; asm("mov.b64 {%0,%1},%2;" : "=f"(lo), "=f"(hi) : "l"(v));
    return make_float2(lo, hi);
}
__device__ __forceinline__ u64 add2(u64 a, u64 b) {
    u64 d; asm("add.rn.f32x2 %0,%1,%2;" : "=l"(d) : "l"(a), "l"(b)); return d;
}
__device__ __forceinline__ u64 fma2(u64 a, u64 b, u64 c) {
    u64 d; asm("fma.rn.f32x2 %0,%1,%2,%3;" : "=l"(d) : "l"(a), "l"(b), "l"(c)); return d;
}
__device__ __forceinline__ u64 abs2(u64 a) {
    u64 d; asm("and.b64 %0,%1,0x7FFFFFFF7FFFFFFF;" : "=l"(d) : "l"(a)); return d;
}

// ---- cluster / DSMEM helpers ----------------------------------------------
__device__ __forceinline__ uint32_t smem_u32(const void* p) {
    uint32_t a;
    asm("{ .reg .u64 t; cvta.to.shared.u64 t, %1; cvt.u32.u64 %0, t; }"
        : "=r"(a) : "l"(p));
    return a;
}
__device__ __forceinline__ uint32_t mapa_rank(uint32_t addr, int rank) {
    uint32_t r;
    asm("mapa.shared::cluster.u32 %0, %1, %2;" : "=r"(r) : "r"(addr), "r"(rank));
    return r;
}
__device__ __forceinline__ float ld_dsmem(uint32_t addr) {
    float v; asm volatile("ld.shared::cluster.f32 %0, [%1];" : "=f"(v) : "r"(addr));
    return v;
}
__device__ __forceinline__ void cluster_arrive_wait() {
    asm volatile("barrier.cluster.arrive.aligned;" ::: "memory");
    asm volatile("barrier.cluster.wait.aligned;"   ::: "memory");
}
__device__ __forceinline__ uint32_t ctarank() {
    uint32_t r; asm("mov.u32 %0, %%cluster_ctarank;" : "=r"(r)); return r;
}

// ---------------------------------------------------------------------------
// One scene == one 8-CTA cluster. No global scratch, no spin locks.
// ---------------------------------------------------------------------------
__global__ void __cluster_dims__(CPS, 1, 1) __launch_bounds__(THREADS, 2)
fusedK(
    const float* __restrict__ x,
    const float* __restrict__ att,
    const float* __restrict__ scale,
    const float* __restrict__ cb,
    const int*   __restrict__ num_objs,
    float*       __restrict__ out,
    int out_size)
{
    __shared__ __align__(16) float sred[4*D_];      // pass1 rowgroup partials (4 KB)
    __shared__ __align__(16) float scol[D_];        // this CTA's column sums (1 KB)
    __shared__ __align__(16) float sctx[D_];        // scene mean context
    __shared__ float sfeat[D_*K_];                  // per-CTA feature partial (2 KB)
    __shared__ __align__(8) float sz[CHUNK*K_];     // per-row z (2 KB)
    __shared__ float szs[K_];                       // per-CTA zsum partial
    __shared__ float sbt[K_];
    __shared__ float stot[K_];                      // scene zsum totals

    const int b     = blockIdx.x >> 3;              // scene = cluster
    const int rank  = ctarank();                    // chunk within scene
    const int tid   = threadIdx.x;
    const int warp  = tid >> 5, lane = tid & 31;

    const uint32_t scol_a  = smem_u32(scol);
    const uint32_t sfeat_a = smem_u32(sfeat);
    const uint32_t szs_a   = smem_u32(szs);

    // ============ pass 1: stream my 256 rows, column sums ==================
    {
        const int col4 = tid & 63;                  // float4 column
        const int rg   = tid >> 6;                  // 0..3
        const float4* x4 = (const float4*)x
            + ((size_t)(b*OBJS_ + rank*CHUNK + rg))*64 + col4;
        float4 acc = {0.f,0.f,0.f,0.f};
        #pragma unroll 16
        for (int i = 0; i < CHUNK/4; i++) {         // stride 4 rows
            float4 v = x4[(size_t)i*256];
            acc.x += v.x; acc.y += v.y; acc.z += v.z; acc.w += v.w;
        }
        *(float4*)&sred[rg*D_ + col4*4] = acc;
    }
    // bias_term (tiny, per-CTA redundant)
    if (tid < 64) {
        int k = tid >> 5, l = tid & 31;
        float s = 0.f;
        #pragma unroll
        for (int j = 0; j < 8; j++) s += cb[k*D_ + l + 32*j] * att[l + 32*j];
        #pragma unroll
        for (int m = 16; m; m >>= 1) s += __shfl_xor_sync(0xffffffffu, s, m);
        if (l == 0) sbt[k] = s;
    }
    __syncthreads();
    scol[tid] = sred[tid] + sred[D_+tid] + sred[2*D_+tid] + sred[3*D_+tid];
    for (int i = tid; i < D_*K_; i += THREADS) sfeat[i] = 0.f;
    if (tid < K_) szs[tid] = 0.f;
    __syncthreads();

    // ============ cluster barrier 1: column sums visible ===================
    cluster_arrive_wait();

    // scene mean context: sum the 8 CTAs' column partials over DSMEM
    {
        const float invc = 1.f / fmaxf((float)num_objs[b], 1.f);
        float s = 0.f;
        #pragma unroll
        for (int j = 0; j < CPS; j++)
            s += ld_dsmem(mapa_rank(scol_a + tid*4, j));
        sctx[tid] = s * invc;
    }
    __syncthreads();

    // ============ pass 2: logits + exp + weighted pooling (L2-hot) =========
    const float bt0 = sbt[0], bt1 = sbt[1];
    const float s0  = scale[0], s1 = scale[1];

    float4 cxa = ((const float4*)sctx)[lane];
    float4 cxb = ((const float4*)sctx)[lane + 32];
    u64 c0 = pack2(cxa.x, cxa.y), c1 = pack2(cxa.z, cxa.w);
    u64 c2 = pack2(cxb.x, cxb.y), c3 = pack2(cxb.z, cxb.w);

    float4 a_a = ((const float4*)att)[lane];
    float4 a_b = ((const float4*)att)[lane + 32];
    // lrelu(t)=0.6t+0.4|t|  ->  a*lrelu = (0.6a)*t + (0.4a)*|t|
    const u64 a6_0 = pack2(0.6f*a_a.x, 0.6f*a_a.y), a6_1 = pack2(0.6f*a_a.z, 0.6f*a_a.w);
    const u64 a6_2 = pack2(0.6f*a_b.x, 0.6f*a_b.y), a6_3 = pack2(0.6f*a_b.z, 0.6f*a_b.w);
    const u64 a4_0 = pack2(0.4f*a_a.x, 0.4f*a_a.y), a4_1 = pack2(0.4f*a_a.z, 0.4f*a_a.w);
    const u64 a4_2 = pack2(0.4f*a_b.x, 0.4f*a_b.y), a4_3 = pack2(0.4f*a_b.z, 0.4f*a_b.w);

    u64 f0_0=0,f0_1=0,f0_2=0,f0_3=0;   // k=0 pooled features (packed)
    u64 f1_0=0,f1_1=0,f1_2=0,f1_3=0;   // k=1
    float zs0 = 0.f, zs1 = 0.f;

    const int rowbase = b*OBJS_ + rank*CHUNK + warp*ROWS_PER_WARP;

    #pragma unroll 4
    for (int r = 0; r < ROWS_PER_WARP; r++) {
        const int lrow = warp*ROWS_PER_WARP + r;
        const ulonglong2* xr = (const ulonglong2*)(x + (size_t)(rowbase + r)*D_);
        ulonglong2 xa = xr[lane];
        ulonglong2 xb = xr[lane + 32];

        u64 t0 = add2(xa.x, c0), t1 = add2(xa.y, c1);
        u64 t2 = add2(xb.x, c2), t3 = add2(xb.y, c3);
        u64 accA = fma2(a6_0, t0, fma2(a4_0, abs2(t0), 0ull));
        accA     = fma2(a6_1, t1, fma2(a4_1, abs2(t1), accA));
        u64 accB = fma2(a6_2, t2, fma2(a4_2, abs2(t2), 0ull));
        accB     = fma2(a6_3, t3, fma2(a4_3, abs2(t3), accB));
        float2 p = unpack2(add2(accA, accB));
        float acc = p.x + p.y;
        #pragma unroll
        for (int m = 16; m; m >>= 1)
            acc += __shfl_xor_sync(0xffffffffu, acc, m);

        float z0 = __expf((acc + bt0) * s0);
        float z1 = __expf((acc + bt1) * s1);
        zs0 += z0; zs1 += z1;
        if (lane == 0) *(float2*)&sz[lrow*2] = make_float2(z0, z1);

        u64 zz0 = pack2(z0, z0), zz1 = pack2(z1, z1);
        f0_0 = fma2(xa.x, zz0, f0_0); f0_1 = fma2(xa.y, zz0, f0_1);
        f0_2 = fma2(xb.x, zz0, f0_2); f0_3 = fma2(xb.y, zz0, f0_3);
        f1_0 = fma2(xa.x, zz1, f1_0); f1_1 = fma2(xa.y, zz1, f1_1);
        f1_2 = fma2(xb.x, zz1, f1_2); f1_3 = fma2(xb.y, zz1, f1_3);
    }

    // cross-warp combine into per-CTA partials (smem atomics)
    {
        int d0 = 4*lane, d1 = 128 + 4*lane;
        float2 v;
        v = unpack2(f0_0); atomicAdd(&sfeat[(d0+0)*2+0], v.x); atomicAdd(&sfeat[(d0+1)*2+0], v.y);
        v = unpack2(f0_1); atomicAdd(&sfeat[(d0+2)*2+0], v.x); atomicAdd(&sfeat[(d0+3)*2+0], v.y);
        v = unpack2(f0_2); atomicAdd(&sfeat[(d1+0)*2+0], v.x); atomicAdd(&sfeat[(d1+1)*2+0], v.y);
        v = unpack2(f0_3); atomicAdd(&sfeat[(d1+2)*2+0], v.x); atomicAdd(&sfeat[(d1+3)*2+0], v.y);
        v = unpack2(f1_0); atomicAdd(&sfeat[(d0+0)*2+1], v.x); atomicAdd(&sfeat[(d0+1)*2+1], v.y);
        v = unpack2(f1_1); atomicAdd(&sfeat[(d0+2)*2+1], v.x); atomicAdd(&sfeat[(d0+3)*2+1], v.y);
        v = unpack2(f1_2); atomicAdd(&sfeat[(d1+0)*2+1], v.x); atomicAdd(&sfeat[(d1+1)*2+1], v.y);
        v = unpack2(f1_3); atomicAdd(&sfeat[(d1+2)*2+1], v.x); atomicAdd(&sfeat[(d1+3)*2+1], v.y);
    }
    if (lane == 0) { atomicAdd(&szs[0], zs0); atomicAdd(&szs[1], zs1); }
    __syncthreads();

    // ============ cluster barrier 2: partials visible ======================
    cluster_arrive_wait();

    // scene zsum totals over DSMEM
    if (tid < K_) {
        float s = 0.f;
        #pragma unroll
        for (int j = 0; j < CPS; j++)
            s += ld_dsmem(mapa_rank(szs_a + tid*4, j));
        stot[tid] = s;
    }
    __syncthreads();
    const float inv0 = 1.f / stot[0], inv1 = 1.f / stot[1];

    const bool full_out = (out_size >= BDK + NK);

    // attention weights: each CTA writes its own 256 rows
    if (full_out || out_size == NK) {
        int obase = full_out ? (BDK/2) : 0;
        float2* o2 = ((float2*)out) + obase + b*OBJS_ + rank*CHUNK;
        const float2* z2 = (const float2*)sz;
        for (int i = tid; i < CHUNK; i += THREADS) {
            float2 z = z2[i];
            o2[i] = make_float2(z.x*inv0, z.y*inv1);
        }
    }

    // scene features: rank r reduces entries [r*64, r*64+64) of the 512-entry
    // [D,K] block over the 8 peers' sfeat partials via DSMEM
    if (out_size >= BDK && tid < 64) {
        int e = rank*64 + tid;                  // e = d*2 + k
        float s = 0.f;
        #pragma unroll
        for (int j = 0; j < CPS; j++)
            s += ld_dsmem(mapa_rank(sfeat_a + e*4, j));
        out[b*(D_*K_) + e] = s * ((e & 1) ? inv1 : inv0);
    }

    // final cluster barrier: no CTA may exit while peers still read its smem
    cluster_arrive_wait();
}

// ---------------------------------------------------------------------------
extern "C" void kernel_launch(void* const* d_in, const int* in_sizes, int n_in,
                              void* d_out, int out_size)
{
    const float* x        = (const float*)d_in[0];  // [N, D]
    const int*   num_objs = (const int*)  d_in[1];  // [B]
    const float* att      = (const float*)d_in[2];  // [1, D]
    const float* scale    = (const float*)d_in[3];  // [K, 1]
    const float* cb       = (const float*)d_in[4];  // [K, D]
    float*       out      = (float*)d_out;

    fusedK<<<NCTA, THREADS>>>(x, att, scale, cb, num_objs, out, out_size);
}